// round 10
// baseline (speedup 1.0000x reference)
#include <cuda_runtime.h>
#include <cstdint>

// Problem constants
#define HDIM   1024
#define DIN    256
#define DOUT   256
#define BATCH  8192
#define NLAYERS 64
#define BK     16

// Scratch (device globals; allocation-free):
__device__ float g_act[2][HDIM * BATCH];                         // activations, m-form, [H, B]
__device__ float g_xm[DIN * BATCH];                              // 2x-1, [DIN, B]
__device__ float g_wtd[(size_t)NLAYERS * HDIM * 2 * HDIM];       // W^T duplicated: [l][k][2m]
__device__ float g_etd[(size_t)DIN * 2 * HDIM];                  // E^T duplicated
__device__ float g_ctd[(size_t)HDIM * 2 * DOUT];                 // C^T duplicated

enum { MODE_EXP = 0, MODE_HID = 1, MODE_OUT = 2 };

typedef unsigned long long u64;

__device__ __forceinline__ void unpack2(u64 v, float& lo, float& hi) {
    asm("mov.b64 {%0, %1}, %2;" : "=f"(lo), "=f"(hi) : "l"(v));
}
__device__ __forceinline__ u64 fma2(u64 a, u64 b, u64 c) {
    u64 d;
    asm("fma.rn.f32x2 %0, %1, %2, %3;" : "=l"(d) : "l"(a), "l"(b), "l"(c));
    return d;
}
__device__ __forceinline__ void cp16(uint32_t dst, const float* src) {
    asm volatile("cp.async.cg.shared.global [%0], [%1], 16;" :: "r"(dst), "l"(src));
}
__device__ __forceinline__ void cp_commit() {
    asm volatile("cp.async.commit_group;");
}
template <int N>
__device__ __forceinline__ void cp_wait() {
    asm volatile("cp.async.wait_group %0;" :: "n"(N));
}

// ---------------- pre-pass kernels ----------------
__global__ void affine_kernel(const float* __restrict__ x, float* __restrict__ xm) {
    int i = blockIdx.x * blockDim.x + threadIdx.x;
    float4 v = ((const float4*)x)[i];
    v.x = 2.0f * v.x - 1.0f; v.y = 2.0f * v.y - 1.0f;
    v.z = 2.0f * v.z - 1.0f; v.w = 2.0f * v.w - 1.0f;
    ((float4*)xm)[i] = v;
}

// in: [R, Cc] (matrix blockIdx.z). out: [Cc, 2R] with out[c][2r] = out[c][2r+1] = in[r][c]
__global__ void transpose_dup_kernel(const float* __restrict__ in, float* __restrict__ out,
                                     int R, int Cc) {
    __shared__ float t[32][33];
    in  += (size_t)blockIdx.z * R * Cc;
    out += (size_t)blockIdx.z * R * Cc * 2;
    int c0 = blockIdx.x * 32, r0 = blockIdx.y * 32;
    int lx = threadIdx.x, ly = threadIdx.y;
    #pragma unroll
    for (int i = 0; i < 32; i += 8)
        t[ly + i][lx] = in[(size_t)(r0 + ly + i) * Cc + c0 + lx];
    __syncthreads();
    #pragma unroll
    for (int i = 0; i < 32; i += 8) {
        float v = t[lx][ly + i];
        *(float2*)&out[(size_t)(c0 + ly + i) * 2 * R + 2 * (r0 + lx)] = make_float2(v, v);
    }
}

// ---------------- main GEMM ----------------
// Atd: [K, 2M] duplicated transposed weights. Bm: [K, N]. C: [M, N].
#define AS_STAGE (BK * 256)     // floats
#define BS_STAGE (BK * 128)
#define BS_BASE  (3 * AS_STAGE)
#define SMEM_BYTES ((3 * AS_STAGE + 3 * BS_STAGE) * 4)

template <int MODE>
__global__ __launch_bounds__(256, 2)
void gemm_kernel(const float* __restrict__ Atd, const float* __restrict__ Bm,
                 float* __restrict__ C, int M, int N, int K)
{
    extern __shared__ float smem[];
    constexpr int TM = 8;

    const int tid = threadIdx.x;
    const int m0 = blockIdx.y * 128;
    const int n0 = blockIdx.x * 128;
    const int tx = tid & 15;      // n direction (x8 cols)
    const int ty = tid >> 4;      // m direction (x8 rows)
    const int AM = 2 * M;         // duplicated row width

    // A loader: 16 rows x 64 chunks(16B); thread covers 4 chunks
    const int al_row = tid >> 4;          // 0..15
    const int al_ch  = tid & 15;          // chunk base
    // B loader: 16 rows x 32 chunks; thread covers 2 (quad-swizzled dst)
    const int bl_row = tid >> 5;          // 0..7 (+8)
    const int bl_q   = tid & 31;
    const int bl_pos = ((bl_q & 1) << 6) | ((bl_q >> 1) << 2);

    u64 acc2[TM][4];
    #pragma unroll
    for (int i = 0; i < TM; i++)
        #pragma unroll
        for (int jp = 0; jp < 4; jp++) acc2[i][jp] = 0ull;

    const int ntiles = K / BK;

    auto load_tile = [&](int s, int t) {
        const int kb = t * BK;
        float* As = smem + s * AS_STAGE;
        float* Bs = smem + BS_BASE + s * BS_STAGE;
        const float* Ag = Atd + (size_t)(kb + al_row) * AM + 2 * m0 + al_ch * 4;
        uint32_t Ad = (uint32_t)__cvta_generic_to_shared(As + al_row * 256 + al_ch * 4);
        #pragma unroll
        for (int it = 0; it < 4; it++)
            cp16(Ad + it * 64 * 4, Ag + it * 64);
        #pragma unroll
        for (int it = 0; it < 2; it++) {
            const int r = bl_row + it * 8;
            cp16((uint32_t)__cvta_generic_to_shared(Bs + r * 128 + bl_pos),
                 Bm + (size_t)(kb + r) * N + n0 + bl_q * 4);
        }
        cp_commit();
    };

    load_tile(0, 0);
    load_tile(1, 1);

    for (int t = 0; t < ntiles; t++) {
        cp_wait<1>();
        __syncthreads();

        if (t + 2 < ntiles) load_tile((t + 2) % 3, t + 2);
        else cp_commit();

        const float* As = smem + (t % 3) * AS_STAGE;
        const float* Bs = smem + BS_BASE + (t % 3) * BS_STAGE;

        #pragma unroll
        for (int k = 0; k < BK; k++) {
            // duplicated A: each u64 is a ready (a,a) pair
            const ulonglong2 a01 = *(const ulonglong2*)&As[k * 256 + ty * 16 + 0];
            const ulonglong2 a23 = *(const ulonglong2*)&As[k * 256 + ty * 16 + 4];
            const ulonglong2 a45 = *(const ulonglong2*)&As[k * 256 + ty * 16 + 8];
            const ulonglong2 a67 = *(const ulonglong2*)&As[k * 256 + ty * 16 + 12];
            // swizzled B: adjacent floats = ready (b0,b1) pairs
            const ulonglong2 b01 = *(const ulonglong2*)&Bs[k * 128 + tx * 4];
            const ulonglong2 b23 = *(const ulonglong2*)&Bs[k * 128 + 64 + tx * 4];

            const u64 aa[8] = { a01.x, a01.y, a23.x, a23.y, a45.x, a45.y, a67.x, a67.y };
            const u64 bp[4] = { b01.x, b01.y, b23.x, b23.y };

            #pragma unroll
            for (int i = 0; i < TM; i++)
                #pragma unroll
                for (int jp = 0; jp < 4; jp++)
                    acc2[i][jp] = fma2(aa[i], bp[jp], acc2[i][jp]);
        }
        __syncthreads();
    }

    // ---- epilogue ----
    #pragma unroll
    for (int i = 0; i < TM; i++) {
        const int row = m0 + ty * TM + i;
        #pragma unroll
        for (int j4 = 0; j4 < 2; j4++) {
            const int col = n0 + tx * 8 + j4 * 4;
            float y[4];
            unpack2(acc2[i][j4 * 2 + 0], y[0], y[1]);
            unpack2(acc2[i][j4 * 2 + 1], y[2], y[3]);
            if (MODE == MODE_HID) {
                float4 r = *(const float4*)(Bm + (size_t)row * N + col);
                y[0] += r.x; y[1] += r.y; y[2] += r.z; y[3] += r.w;
            }
            float4 o;
            #pragma unroll
            for (int q = 0; q < 4; q++) {
                float v = fminf(fmaxf(y[q], 0.0f), 1.0f);
                if (MODE != MODE_OUT) v = 2.0f * v - 1.0f;
                ((float*)&o)[q] = v;
            }
            *(float4*)(C + (size_t)row * N + col) = o;
        }
    }
}

extern "C" void kernel_launch(void* const* d_in, const int* in_sizes, int n_in,
                              void* d_out, int out_size)
{
    const float* x           = (const float*)d_in[0]; // [DIN, BATCH]
    const float* expansion   = (const float*)d_in[1]; // [HDIM, DIN]
    const float* hidden      = (const float*)d_in[2]; // [NLAYERS, HDIM, HDIM]
    const float* compression = (const float*)d_in[3]; // [DOUT, HDIM]
    float* out = (float*)d_out;                        // [DOUT, BATCH]

    float *act0, *xm, *wtd, *etd, *ctd;
    cudaGetSymbolAddress((void**)&act0, g_act);
    cudaGetSymbolAddress((void**)&xm, g_xm);
    cudaGetSymbolAddress((void**)&wtd, g_wtd);
    cudaGetSymbolAddress((void**)&etd, g_etd);
    cudaGetSymbolAddress((void**)&ctd, g_ctd);
    float* act1 = act0 + (size_t)HDIM * BATCH;

    cudaFuncSetAttribute(gemm_kernel<MODE_EXP>, cudaFuncAttributeMaxDynamicSharedMemorySize, SMEM_BYTES);
    cudaFuncSetAttribute(gemm_kernel<MODE_HID>, cudaFuncAttributeMaxDynamicSharedMemorySize, SMEM_BYTES);
    cudaFuncSetAttribute(gemm_kernel<MODE_OUT>, cudaFuncAttributeMaxDynamicSharedMemorySize, SMEM_BYTES);

    // ---- pre-pass ----
    affine_kernel<<<(DIN * BATCH / 4) / 256, 256>>>(x, xm);
    transpose_dup_kernel<<<dim3(DIN / 32, HDIM / 32, 1), dim3(32, 8)>>>(expansion, etd, HDIM, DIN);
    transpose_dup_kernel<<<dim3(HDIM / 32, HDIM / 32, NLAYERS), dim3(32, 8)>>>(hidden, wtd, HDIM, HDIM);
    transpose_dup_kernel<<<dim3(HDIM / 32, DOUT / 32, 1), dim3(32, 8)>>>(compression, ctd, DOUT, HDIM);

    dim3 blk(256);

    // Expansion
    gemm_kernel<MODE_EXP><<<dim3(BATCH / 128, HDIM / 128), blk, SMEM_BYTES>>>(
        etd, xm, act0, HDIM, BATCH, DIN);

    // Hidden layers
    float* cur = act0;
    float* nxt = act1;
    for (int l = 0; l < NLAYERS; l++) {
        gemm_kernel<MODE_HID><<<dim3(BATCH / 128, HDIM / 128), blk, SMEM_BYTES>>>(
            wtd + (size_t)l * HDIM * 2 * HDIM, cur, nxt, HDIM, BATCH, HDIM);
        float* tmp = cur; cur = nxt; nxt = tmp;
    }

    // Compression
    gemm_kernel<MODE_OUT><<<dim3(BATCH / 128, DOUT / 128), blk, SMEM_BYTES>>>(
        ctd, cur, out, DOUT, BATCH, HDIM);
}

// round 11
// speedup vs baseline: 1.1520x; 1.1520x over previous
#include <cuda_runtime.h>
#include <cstdint>

// Problem constants
#define HDIM   1024
#define DIN    256
#define DOUT   256
#define BATCH  8192
#define NLAYERS 64
#define BK     16

// Scratch (device globals; allocation-free):
__device__ float g_act[2][HDIM * BATCH];                     // activations, m = 2h-1 form, [H, B]
__device__ float g_xm[DIN * BATCH];                          // 2x-1, [DIN, B]
__device__ float g_wt[(size_t)NLAYERS * HDIM * HDIM];        // W transposed: [l][k][m]
__device__ float g_et[(size_t)DIN * HDIM];                   // E transposed: [k][m]
__device__ float g_ct[(size_t)HDIM * DOUT];                  // C transposed: [k][m]

enum { MODE_EXP = 0, MODE_HID = 1, MODE_OUT = 2 };

typedef unsigned long long u64;

__device__ __forceinline__ u64 pack2(float lo, float hi) {
    u64 r;
    asm("mov.b64 %0, {%1, %2};" : "=l"(r) : "f"(lo), "f"(hi));
    return r;
}
__device__ __forceinline__ void unpack2(u64 v, float& lo, float& hi) {
    asm("mov.b64 {%0, %1}, %2;" : "=f"(lo), "=f"(hi) : "l"(v));
}
__device__ __forceinline__ u64 fma2(u64 a, u64 b, u64 c) {
    u64 d;
    asm("fma.rn.f32x2 %0, %1, %2, %3;" : "=l"(d) : "l"(a), "l"(b), "l"(c));
    return d;
}
__device__ __forceinline__ void cp16(uint32_t dst, const float* src) {
    asm volatile("cp.async.cg.shared.global [%0], [%1], 16;" :: "r"(dst), "l"(src));
}
__device__ __forceinline__ void cp_commit() {
    asm volatile("cp.async.commit_group;");
}
template <int N>
__device__ __forceinline__ void cp_wait() {
    asm volatile("cp.async.wait_group %0;" :: "n"(N));
}

// ---------------- pre-pass kernels ----------------
__global__ void affine_kernel(const float* __restrict__ x, float* __restrict__ xm) {
    int i = blockIdx.x * blockDim.x + threadIdx.x;
    float4 v = ((const float4*)x)[i];
    v.x = 2.0f * v.x - 1.0f; v.y = 2.0f * v.y - 1.0f;
    v.z = 2.0f * v.z - 1.0f; v.w = 2.0f * v.w - 1.0f;
    ((float4*)xm)[i] = v;
}

// out[c][r] = in[r][c] for matrix blockIdx.z of shape [R, Cc]
__global__ void transpose_kernel(const float* __restrict__ in, float* __restrict__ out,
                                 int R, int Cc) {
    __shared__ float t[32][33];
    const size_t off = (size_t)blockIdx.z * R * Cc;
    in += off; out += off;
    int c0 = blockIdx.x * 32, r0 = blockIdx.y * 32;
    int lx = threadIdx.x, ly = threadIdx.y;
    #pragma unroll
    for (int i = 0; i < 32; i += 8)
        t[ly + i][lx] = in[(size_t)(r0 + ly + i) * Cc + c0 + lx];
    __syncthreads();
    #pragma unroll
    for (int i = 0; i < 32; i += 8)
        out[(size_t)(c0 + ly + i) * R + r0 + lx] = t[lx][ly + i];
}

// ---------------- main GEMM ----------------
// At: [K, M] (transposed weights). Bm: [K, N]. C: [M, N].
template <int MODE>
__global__ __launch_bounds__(256, 2)
void gemm_kernel(const float* __restrict__ At, const float* __restrict__ Bm,
                 float* __restrict__ C, int M, int N, int K)
{
    constexpr int TM = 8;
    __shared__ float As[3][BK][128];
    __shared__ float Bs[3][BK][128];   // quad-swizzled columns

    const int tid = threadIdx.x;
    const int m0 = blockIdx.y * 128;
    const int n0 = blockIdx.x * 128;
    const int tx = tid & 15;      // n direction (x8 cols)
    const int ty = tid >> 4;      // m direction (x8 rows)

    // loader coords: 2 chunks of 16B per thread per tile per matrix
    const int l_row = tid >> 5;           // 0..7 (+8)
    const int l_q   = tid & 31;
    const int a_col = l_q * 4;
    const int b_pos = ((l_q & 1) << 6) | ((l_q >> 1) << 2);   // quad swizzle

    u64 acc2[TM][4];
    #pragma unroll
    for (int i = 0; i < TM; i++)
        #pragma unroll
        for (int jp = 0; jp < 4; jp++) acc2[i][jp] = 0ull;

    const int ntiles = K / BK;

    auto load_tile = [&](int s, int t) {
        const int kb = t * BK;
        #pragma unroll
        for (int it = 0; it < 2; it++) {
            const int r = l_row + it * 8;
            cp16((uint32_t)__cvta_generic_to_shared(&As[s][r][a_col]),
                 At + (size_t)(kb + r) * M + m0 + a_col);
            cp16((uint32_t)__cvta_generic_to_shared(&Bs[s][r][b_pos]),
                 Bm + (size_t)(kb + r) * N + n0 + l_q * 4);
        }
        cp_commit();
    };

    load_tile(0, 0);
    load_tile(1, 1);

    for (int t = 0; t < ntiles; t++) {
        cp_wait<1>();
        // single barrier per tile: also guarantees all warps finished compute
        // on stage (t-1)%3 == (t+2)%3 before we overwrite it below.
        __syncthreads();

        if (t + 2 < ntiles) load_tile((t + 2) % 3, t + 2);
        else cp_commit();   // keep group count uniform

        const int cur = t % 3;

        #pragma unroll
        for (int k = 0; k < BK; k++) {
            float a[TM];
            *(float4*)&a[0] = *(const float4*)&As[cur][k][ty * TM];
            *(float4*)&a[4] = *(const float4*)&As[cur][k][ty * TM + 4];
            // direct packed B operands (quad-swizzle keeps 16B units intact)
            const ulonglong2 b01 = *(const ulonglong2*)&Bs[cur][k][tx * 4];
            const ulonglong2 b23 = *(const ulonglong2*)&Bs[cur][k][64 + tx * 4];
            const u64 bp[4] = { b01.x, b01.y, b23.x, b23.y };

            #pragma unroll
            for (int i = 0; i < TM; i++) {
                const u64 aa = pack2(a[i], a[i]);
                #pragma unroll
                for (int jp = 0; jp < 4; jp++)
                    acc2[i][jp] = fma2(aa, bp[jp], acc2[i][jp]);
            }
        }
        // no trailing barrier: 3-stage ring + top barrier make it redundant
    }

    // ---- epilogue ----
    #pragma unroll
    for (int i = 0; i < TM; i++) {
        const int row = m0 + ty * TM + i;
        #pragma unroll
        for (int j4 = 0; j4 < 2; j4++) {
            const int col = n0 + tx * 8 + j4 * 4;
            float y[4];
            unpack2(acc2[i][j4 * 2 + 0], y[0], y[1]);
            unpack2(acc2[i][j4 * 2 + 1], y[2], y[3]);
            if (MODE == MODE_HID) {
                float4 r = *(const float4*)(Bm + (size_t)row * N + col);
                y[0] += r.x; y[1] += r.y; y[2] += r.z; y[3] += r.w;
            }
            float4 o;
            #pragma unroll
            for (int q = 0; q < 4; q++) {
                float v = fminf(fmaxf(y[q], 0.0f), 1.0f);
                if (MODE != MODE_OUT) v = 2.0f * v - 1.0f;
                ((float*)&o)[q] = v;
            }
            *(float4*)(C + (size_t)row * N + col) = o;
        }
    }
}

extern "C" void kernel_launch(void* const* d_in, const int* in_sizes, int n_in,
                              void* d_out, int out_size)
{
    const float* x           = (const float*)d_in[0]; // [DIN, BATCH]
    const float* expansion   = (const float*)d_in[1]; // [HDIM, DIN]
    const float* hidden      = (const float*)d_in[2]; // [NLAYERS, HDIM, HDIM]
    const float* compression = (const float*)d_in[3]; // [DOUT, HDIM]
    float* out = (float*)d_out;                        // [DOUT, BATCH]

    float *act0, *xm, *wt, *et, *ct;
    cudaGetSymbolAddress((void**)&act0, g_act);
    cudaGetSymbolAddress((void**)&xm, g_xm);
    cudaGetSymbolAddress((void**)&wt, g_wt);
    cudaGetSymbolAddress((void**)&et, g_et);
    cudaGetSymbolAddress((void**)&ct, g_ct);
    float* act1 = act0 + (size_t)HDIM * BATCH;

    // ---- pre-pass: affine input + transpose all weight matrices ----
    affine_kernel<<<(DIN * BATCH / 4) / 256, 256>>>(x, xm);
    transpose_kernel<<<dim3(DIN / 32, HDIM / 32, 1), dim3(32, 8)>>>(expansion, et, HDIM, DIN);
    transpose_kernel<<<dim3(HDIM / 32, HDIM / 32, NLAYERS), dim3(32, 8)>>>(hidden, wt, HDIM, HDIM);
    transpose_kernel<<<dim3(HDIM / 32, DOUT / 32, 1), dim3(32, 8)>>>(compression, ct, DOUT, HDIM);

    dim3 blk(256);

    // Expansion: m0 = 2*clip(E @ (2x-1)) - 1
    gemm_kernel<MODE_EXP><<<dim3(BATCH / 128, HDIM / 128), blk>>>(
        et, xm, act0, HDIM, BATCH, DIN);

    // 64 hidden layers: m' = 2*clip(W m + m) - 1
    float* cur = act0;
    float* nxt = act1;
    for (int l = 0; l < NLAYERS; l++) {
        gemm_kernel<MODE_HID><<<dim3(BATCH / 128, HDIM / 128), blk>>>(
            wt + (size_t)l * HDIM * HDIM, cur, nxt, HDIM, BATCH, HDIM);
        float* tmp = cur; cur = nxt; nxt = tmp;
    }

    // Compression: out = clip(Cmp @ m)
    gemm_kernel<MODE_OUT><<<dim3(BATCH / 128, DOUT / 128), blk>>>(
        ct, cur, out, DOUT, BATCH, HDIM);
}